// round 2
// baseline (speedup 1.0000x reference)
#include <cuda_runtime.h>
#include <cstdint>

#define HN       128
#define BATCH    1024
#define SEQT     512
#define CL       8            // cluster size (CTAs per cluster)
#define MROWS    64           // batch rows per cluster (per CTA M)
#define NTHREADS 128
#define SA       260          // A-tile row stride in floats (260 mod 32 = 4 -> conflict-free frag LDS)

// ---- shared memory layout (float offsets) ----
#define OF_A    0                      // A tile [64][260] = 16640 floats ([h1 | h2] K=256 + pad)
#define OF_B1   (64 * SA)              // layer-1 B frags: 4g x 2qnt x 8ktp x 32lane x 4 = 8192 floats
#define OF_B2   (OF_B1 + 8192)         // layer-2 B frags: 4g x 2qnt x 16ktp x 32 x 4 = 16384 floats
#define OF_WX   (OF_B2 + 16384)        // Wih1 slice [4][16]
#define OF_BB1  (OF_WX + 64)           // bih1+bhh1 slice [4][16]
#define OF_BB2  (OF_BB1 + 64)          // bih2+bhh2 slice [4][16]
#define SMEM_FLOATS (OF_BB2 + 64)
#define SMEM_BYTES  (SMEM_FLOATS * 4)  // 165,888 B

// ---- device scratch (allocation-free) ----
__device__ float g_xT[SEQT * BATCH];   // x transposed to [T, B]
__device__ float g_h1[BATCH * HN];
__device__ float g_h2[BATCH * HN];

// ======================= helpers =======================
__device__ __forceinline__ float tf32r(float v) {
    float o; asm("cvt.rna.tf32.f32 %0, %1;" : "=f"(o) : "f"(v)); return o;
}
#define CLUSTER_SYNC() do { \
    asm volatile("barrier.cluster.arrive.aligned;" ::: "memory"); \
    asm volatile("barrier.cluster.wait.aligned;" ::: "memory"); } while (0)

// D += A(16x8) * B(8x8), tf32 in fp32 containers, fp32 accumulate
__device__ __forceinline__ void mma8(float* d, const uint32_t* a, uint32_t b0, uint32_t b1) {
    asm volatile(
        "mma.sync.aligned.m16n8k8.row.col.f32.tf32.tf32.f32 "
        "{%0,%1,%2,%3}, {%4,%5,%6,%7}, {%8,%9}, {%0,%1,%2,%3};"
        : "+f"(d[0]), "+f"(d[1]), "+f"(d[2]), "+f"(d[3])
        : "r"(a[0]), "r"(a[1]), "r"(a[2]), "r"(a[3]), "r"(b0), "r"(b1));
}

__device__ __forceinline__ float sigf(float x) {
    float e = __expf(-x);
    return __fdividef(1.0f, 1.0f + e);
}
__device__ __forceinline__ float tanhe(float x) {
    float e = __expf(-2.0f * x);
    return 2.0f * __fdividef(1.0f, 1.0f + e) - 1.0f;
}

// MMA phase: acc[gate][mt][4] += A[mbase.., cols 0..KTP*16) x Bfrag
template <int KTP>
__device__ __forceinline__ void mma_phase(float acc[4][2][4], const float* As, const float* Bf,
                                          int mbase, int g, int tq, int qhalf, int lane) {
    const uint32_t* Au = (const uint32_t*)As;
    const float4*   Bv = (const float4*)Bf;
#pragma unroll 2
    for (int ktp = 0; ktp < KTP; ktp++) {
        uint32_t a[2][2][4];  // [kt-in-pair][mt][reg]
#pragma unroll
        for (int mt = 0; mt < 2; mt++) {
            int base = (mbase + mt * 16 + g) * SA + ktp * 16 + tq;
#pragma unroll
            for (int kti = 0; kti < 2; kti++) {
                a[kti][mt][0] = Au[base + kti * 8];
                a[kti][mt][1] = Au[base + kti * 8 + 8 * SA];
                a[kti][mt][2] = Au[base + kti * 8 + 4];
                a[kti][mt][3] = Au[base + kti * 8 + 8 * SA + 4];
            }
        }
#pragma unroll
        for (int gt = 0; gt < 4; gt++) {
            float4 bv = Bv[(((gt * 2 + qhalf) * KTP) + ktp) * 32 + lane];
            uint32_t bx = __float_as_uint(bv.x), by = __float_as_uint(bv.y);
            uint32_t bz = __float_as_uint(bv.z), bw = __float_as_uint(bv.w);
            mma8(acc[gt][0], a[0][0], bx, by);
            mma8(acc[gt][1], a[0][1], bx, by);
            mma8(acc[gt][0], a[1][0], bz, bw);
            mma8(acc[gt][1], a[1][1], bz, bw);
        }
    }
}

// gather h (M=64 x 128 dims) from global into A-tile cols [dstcol, dstcol+128)
__device__ __forceinline__ void gather_h(float* As, const float* src, int dstcol, int tid, int b0) {
    int r = tid >> 1, half = tid & 1;
    const float4* s = (const float4*)(src + (size_t)(b0 + r) * HN + half * 64);
    float4* d = (float4*)(As + r * SA + dstcol + half * 64);
#pragma unroll
    for (int j = 0; j < 16; j++) {
        float4 v = __ldcg(s + j);
        v.x = tf32r(v.x); v.y = tf32r(v.y); v.z = tf32r(v.z); v.w = tf32r(v.w);
        d[j] = v;
    }
}

// ======================= kernels =======================
__global__ void xT_kernel(const float* __restrict__ x) {
    int i = blockIdx.x * blockDim.x + threadIdx.x;   // i = t*1024 + b (writes coalesced)
    if (i < BATCH * SEQT) {
        int tt = i >> 10, b = i & 1023;
        g_xT[i] = x[b * SEQT + tt];
    }
}

extern "C" __global__ void __launch_bounds__(NTHREADS, 1) __cluster_dims__(CL, 1, 1)
lstm2_kernel(const float* __restrict__ Wih1, const float* __restrict__ Whh1,
             const float* __restrict__ bih1, const float* __restrict__ bhh1,
             const float* __restrict__ Wih2, const float* __restrict__ Whh2,
             const float* __restrict__ bih2, const float* __restrict__ bhh2,
             const float* __restrict__ Wl,   const float* __restrict__ bl,
             float* __restrict__ out)
{
    extern __shared__ float sm[];
    const int tid  = threadIdx.x;
    const int lane = tid & 31;
    const int wid  = tid >> 5;
    const int g    = lane >> 2;     // frag group row
    const int tq   = lane & 3;      // frag thread-in-group
    const int mhalf = wid >> 1, qhalf = wid & 1;
    const int mbase = mhalf * 32;
    const int rank = blockIdx.x & (CL - 1);
    const int b0   = (blockIdx.x / CL) * MROWS;

    float* As  = sm + OF_A;
    float* B1f = sm + OF_B1;
    float* B2f = sm + OF_B2;
    float* WX  = sm + OF_WX;
    float* BB1 = sm + OF_BB1;
    float* BB2 = sm + OF_BB2;

    // ---- pack weight slices in mma-fragment order (tf32-rounded) ----
    // CTA owns hidden dims [rank*16, rank*16+16); gates stored as 4 separate N-blocks.
    for (int idx = tid; idx < 8192; idx += NTHREADS) {          // layer-1 (K=128, ktp 0..7)
        int j = idx & 3, ln = (idx >> 2) & 31, ktp = (idx >> 7) & 7;
        int qnt = (idx >> 10) & 1, gate = idx >> 11;
        int k = (2 * ktp + (j >> 1)) * 8 + (ln & 3) + 4 * (j & 1);
        int q = qnt * 8 + (ln >> 2);
        int gr = gate * HN + rank * 16 + q;
        B1f[idx] = tf32r(Whh1[gr * HN + k]);
    }
    for (int idx = tid; idx < 16384; idx += NTHREADS) {         // layer-2 (K=256, ktp 0..15)
        int j = idx & 3, ln = (idx >> 2) & 31, ktp = (idx >> 7) & 15;
        int qnt = (idx >> 11) & 1, gate = idx >> 12;
        int k = (2 * ktp + (j >> 1)) * 8 + (ln & 3) + 4 * (j & 1);
        int q = qnt * 8 + (ln >> 2);
        int gr = gate * HN + rank * 16 + q;
        float v = (k < HN) ? Wih2[gr * HN + k] : Whh2[gr * HN + (k - HN)];
        B2f[idx] = tf32r(v);
    }
    if (tid < 64) {
        int gt = tid >> 4, q = tid & 15;
        int gr = gt * HN + rank * 16 + q;
        WX[tid]  = Wih1[gr];            // IN = 1
        BB1[tid] = bih1[gr] + bhh1[gr];
        BB2[tid] = bih2[gr] + bhh2[gr];
    }
    for (int i = tid; i < 64 * SA; i += NTHREADS) As[i] = 0.0f;  // h1=h2=0
    __syncthreads();

    // per-thread state: 4 rows x 2 q-dims = 8 cells per layer
    float c1[8], c2[8];
#pragma unroll
    for (int i = 0; i < 8; i++) { c1[i] = 0.f; c2[i] = 0.f; }

    int rows[4];
#pragma unroll
    for (int mt = 0; mt < 2; mt++)
#pragma unroll
        for (int rr = 0; rr < 2; rr++)
            rows[mt * 2 + rr] = mbase + mt * 16 + g + 8 * rr;

    for (int t = 0; t < SEQT; t++) {
        // prefetch x_t for this thread's rows (L2-resident)
        float xtv[4];
#pragma unroll
        for (int e = 0; e < 4; e++) xtv[e] = __ldcg(&g_xT[t * BATCH + b0 + rows[e]]);

        // ================= layer 1: gates = h1 @ Whh1^T (A cols 0:128) =================
        float acc[4][2][4];
#pragma unroll
        for (int a1 = 0; a1 < 4; a1++)
#pragma unroll
            for (int a2 = 0; a2 < 2; a2++)
#pragma unroll
                for (int a3 = 0; a3 < 4; a3++) acc[a1][a2][a3] = 0.f;
        mma_phase<8>(acc, As, B1f, mbase, g, tq, qhalf, lane);

#pragma unroll
        for (int mt = 0; mt < 2; mt++) {
#pragma unroll
            for (int rr = 0; rr < 2; rr++) {
                int e = mt * 2 + rr;
                float hp[2];
#pragma unroll
                for (int qq = 0; qq < 2; qq++) {
                    int fr = rr * 2 + qq;
                    int qloc = qhalf * 8 + tq * 2 + qq;
                    float gi = acc[0][mt][fr] + xtv[e] * WX[qloc]      + BB1[qloc];
                    float gf = acc[1][mt][fr] + xtv[e] * WX[16 + qloc] + BB1[16 + qloc];
                    float gg = acc[2][mt][fr] + xtv[e] * WX[32 + qloc] + BB1[32 + qloc];
                    float go = acc[3][mt][fr] + xtv[e] * WX[48 + qloc] + BB1[48 + qloc];
                    float iv = sigf(gi), fv = sigf(gf), gv = tanhe(gg), ov = sigf(go);
                    int ci = e * 2 + qq;
                    c1[ci] = fv * c1[ci] + iv * gv;
                    hp[qq] = ov * tanhe(c1[ci]);
                }
                float2* dst = (float2*)(g_h1 + (size_t)(b0 + rows[e]) * HN
                                        + rank * 16 + qhalf * 8 + tq * 2);
                *dst = make_float2(hp[0], hp[1]);
            }
        }
        __threadfence();
        CLUSTER_SYNC();
        gather_h(As, g_h1, 0, tid, b0);     // h1(t) -> A cols 0:128
        __syncthreads();

        // ============ layer 2: gates = [h1(t)|h2(t-1)] @ [Wih2|Whh2]^T (A cols 0:256) ============
#pragma unroll
        for (int a1 = 0; a1 < 4; a1++)
#pragma unroll
            for (int a2 = 0; a2 < 2; a2++)
#pragma unroll
                for (int a3 = 0; a3 < 4; a3++) acc[a1][a2][a3] = 0.f;
        mma_phase<16>(acc, As, B2f, mbase, g, tq, qhalf, lane);

#pragma unroll
        for (int mt = 0; mt < 2; mt++) {
#pragma unroll
            for (int rr = 0; rr < 2; rr++) {
                int e = mt * 2 + rr;
                float hp[2];
#pragma unroll
                for (int qq = 0; qq < 2; qq++) {
                    int fr = rr * 2 + qq;
                    int qloc = qhalf * 8 + tq * 2 + qq;
                    float gi = acc[0][mt][fr] + BB2[qloc];
                    float gf = acc[1][mt][fr] + BB2[16 + qloc];
                    float gg = acc[2][mt][fr] + BB2[32 + qloc];
                    float go = acc[3][mt][fr] + BB2[48 + qloc];
                    float iv = sigf(gi), fv = sigf(gf), gv = tanhe(gg), ov = sigf(go);
                    int ci = e * 2 + qq;
                    c2[ci] = fv * c2[ci] + iv * gv;
                    hp[qq] = ov * tanhe(c2[ci]);
                }
                float2* dst = (float2*)(g_h2 + (size_t)(b0 + rows[e]) * HN
                                        + rank * 16 + qhalf * 8 + tq * 2);
                *dst = make_float2(hp[0], hp[1]);
            }
        }
        __threadfence();
        CLUSTER_SYNC();
        gather_h(As, g_h2, 128, tid, b0);   // h2(t) -> A cols 128:256
        __syncthreads();
    }

    // ---- final linear: out[b] = h2[b,:] . Wl + bl ----
    if (rank == 0 && tid < MROWS) {
        const float* h2r = g_h2 + (size_t)(b0 + tid) * HN;
        float acc = bl[0];
#pragma unroll 16
        for (int k = 0; k < HN; k++) acc += __ldcg(&h2r[k]) * __ldg(&Wl[k]);
        out[b0 + tid] = acc;
    }
}

// ======================= launch =======================
extern "C" void kernel_launch(void* const* d_in, const int* in_sizes, int n_in,
                              void* d_out, int out_size) {
    const float* x    = (const float*)d_in[0];
    const float* Wih1 = (const float*)d_in[1];
    const float* Whh1 = (const float*)d_in[2];
    const float* bih1 = (const float*)d_in[3];
    const float* bhh1 = (const float*)d_in[4];
    const float* Wih2 = (const float*)d_in[5];
    const float* Whh2 = (const float*)d_in[6];
    const float* bih2 = (const float*)d_in[7];
    const float* bhh2 = (const float*)d_in[8];
    const float* Wl   = (const float*)d_in[9];
    const float* bl   = (const float*)d_in[10];
    float* out = (float*)d_out;

    cudaFuncSetAttribute(lstm2_kernel, cudaFuncAttributeMaxDynamicSharedMemorySize, SMEM_BYTES);

    xT_kernel<<<(BATCH * SEQT + 255) / 256, 256>>>(x);
    lstm2_kernel<<<(BATCH / MROWS) * CL, NTHREADS, SMEM_BYTES>>>(
        Wih1, Whh1, bih1, bhh1, Wih2, Whh2, bih2, bhh2, Wl, bl, out);
}

// round 5
// speedup vs baseline: 2.5041x; 2.5041x over previous
#include <cuda_runtime.h>
#include <cuda_fp16.h>
#include <cstdint>

#define HN       128
#define BATCH    1024
#define SEQT     512
#define CL       8            // CTAs per cluster
#define MROWS    64           // batch rows per cluster
#define NTHREADS 128

#define SAW      132          // A-tile row stride in 32-bit words (264 fp16 = 528 B)

// ---- shared memory layout (32-bit word offsets) ----
#define OF_A     0                       // A tile [64][264 fp16] = 8448 words
#define OF_B1    (64 * SAW)              // layer-1 B frags: 4096 words (16 KB)
#define OF_B2    (OF_B1 + 4096)          // layer-2 B frags: 8192 words (32 KB)
#define OF_WX    (OF_B2 + 8192)          // Wih1 slice   [64] floats
#define OF_BB1   (OF_WX + 64)            // bih1+bhh1    [64] floats
#define OF_BB2   (OF_BB1 + 64)           // bih2+bhh2    [64] floats
#define SMEM_WORDS (OF_BB2 + 64)
#define SMEM_BYTES (SMEM_WORDS * 4)      // 83,712 B

// ---- device scratch (allocation-free) ----
__device__ float    g_xT[SEQT * BATCH];      // x transposed to [T, B]
__device__ uint32_t g_h[2][BATCH * 128];     // double-buffered: per row 128 words = [h1 | h2] fp16

// ======================= helpers =======================
__device__ __forceinline__ uint32_t smem_u32(const void* p) {
    uint32_t a;
    asm("{ .reg .u64 t; cvta.to.shared.u64 t, %1; cvt.u32.u64 %0, t; }" : "=r"(a) : "l"(p));
    return a;
}
#define CLUSTER_ARRIVE() asm volatile("barrier.cluster.arrive.aligned;" ::: "memory")
#define CLUSTER_WAIT()   asm volatile("barrier.cluster.wait.aligned;" ::: "memory")

__device__ __forceinline__ void mmaf16(float* d, const uint32_t* a, uint32_t b0, uint32_t b1) {
    asm volatile(
        "mma.sync.aligned.m16n8k16.row.col.f32.f16.f16.f32 "
        "{%0,%1,%2,%3}, {%4,%5,%6,%7}, {%8,%9}, {%0,%1,%2,%3};"
        : "+f"(d[0]), "+f"(d[1]), "+f"(d[2]), "+f"(d[3])
        : "r"(a[0]), "r"(a[1]), "r"(a[2]), "r"(a[3]), "r"(b0), "r"(b1));
}
__device__ __forceinline__ void ldmA(uint32_t* r, uint32_t addr) {
    asm volatile("ldmatrix.sync.aligned.m8n8.x4.shared.b16 {%0,%1,%2,%3}, [%4];"
                 : "=r"(r[0]), "=r"(r[1]), "=r"(r[2]), "=r"(r[3]) : "r"(addr));
}
__device__ __forceinline__ float sigf(float x) {
    float e = __expf(-x);
    return __fdividef(1.0f, 1.0f + e);
}
__device__ __forceinline__ float tanhe(float x) {
    float e = __expf(-2.0f * x);
    return 2.0f * __fdividef(1.0f, 1.0f + e) - 1.0f;
}

// ======================= kernels =======================
__global__ void xT_kernel(const float* __restrict__ x) {
    int i = blockIdx.x * blockDim.x + threadIdx.x;   // i = t*1024 + b (coalesced writes)
    if (i < BATCH * SEQT) {
        int tt = i >> 10, b = i & 1023;
        g_xT[i] = x[b * SEQT + tt];
    }
}

extern "C" __global__ void __launch_bounds__(NTHREADS, 1) __cluster_dims__(CL, 1, 1)
lstm2_kernel(const float* __restrict__ Wih1, const float* __restrict__ Whh1,
             const float* __restrict__ bih1, const float* __restrict__ bhh1,
             const float* __restrict__ Wih2, const float* __restrict__ Whh2,
             const float* __restrict__ bih2, const float* __restrict__ bhh2,
             const float* __restrict__ Wl,   const float* __restrict__ bl,
             float* __restrict__ out)
{
    extern __shared__ uint32_t sm[];
    const int tid  = threadIdx.x;
    const int lane = tid & 31;
    const int wid  = tid >> 5;
    const int g    = lane >> 2;
    const int tq   = lane & 3;
    const int mhalf = wid >> 1, qh = wid & 1;
    const int mbase = mhalf * 32;
    const int rank = blockIdx.x & (CL - 1);
    const int b0   = (blockIdx.x / CL) * MROWS;

    float* WX  = (float*)(sm + OF_WX);
    float* BB1 = (float*)(sm + OF_BB1);
    float* BB2 = (float*)(sm + OF_BB2);

    // ---- pack weight slices into fp16 mma-fragment order ----
    // Consumption: uint4 U = ((q2*KTP + ktp)*2 + p)*32 + lane  -> word = 4*U + j
    // decode: j = idx&3, lane = (idx>>2)&31, p = (idx>>7)&1, ktp next, q2 top.
    // Fragment: gate = p*2 + (j>>1), reg = j&1;
    // B[k][n]: k0 = ktp*16 + reg*8 + 2*(lane&3), n = q2*8 + (lane>>2)
    for (int idx = tid; idx < 4096; idx += NTHREADS) {          // layer 1 (K=128)
        int j = idx & 3, ln = (idx >> 2) & 31, p = (idx >> 7) & 1;
        int ktp = (idx >> 8) & 7, q2 = idx >> 11;
        int gate = p * 2 + (j >> 1), reg = j & 1;
        int gg = ln >> 2, ttq = ln & 3;
        int k0 = ktp * 16 + reg * 8 + 2 * ttq;
        int gr = gate * HN + rank * 16 + q2 * 8 + gg;
        __half2 hv = __floats2half2_rn(Whh1[gr * HN + k0], Whh1[gr * HN + k0 + 1]);
        sm[OF_B1 + idx] = *(uint32_t*)&hv;
    }
    for (int idx = tid; idx < 8192; idx += NTHREADS) {          // layer 2 (K=256)
        int j = idx & 3, ln = (idx >> 2) & 31, p = (idx >> 7) & 1;
        int ktp = (idx >> 8) & 15, q2 = idx >> 12;
        int gate = p * 2 + (j >> 1), reg = j & 1;
        int gg = ln >> 2, ttq = ln & 3;
        int k0 = ktp * 16 + reg * 8 + 2 * ttq;
        int gr = gate * HN + rank * 16 + q2 * 8 + gg;
        float w0 = (k0 < HN)     ? Wih2[gr * HN + k0]     : Whh2[gr * HN + k0 - HN];
        float w1 = (k0 + 1 < HN) ? Wih2[gr * HN + k0 + 1] : Whh2[gr * HN + k0 + 1 - HN];
        __half2 hv = __floats2half2_rn(w0, w1);
        sm[OF_B2 + idx] = *(uint32_t*)&hv;
    }
    if (tid < 64) {
        int gt = tid >> 4, q = tid & 15;
        int gr = gt * HN + rank * 16 + q;
        WX[tid]  = Wih1[gr];
        BB1[tid] = bih1[gr] + bhh1[gr];
        BB2[tid] = bih2[gr] + bhh2[gr];
    }
    for (int i = tid; i < 64 * SAW; i += NTHREADS) sm[OF_A + i] = 0u;   // h1=h2=0
    __syncthreads();

    // per-thread rows and addresses
    int rows[4];
#pragma unroll
    for (int mt = 0; mt < 2; mt++)
#pragma unroll
        for (int rr = 0; rr < 2; rr++)
            rows[mt * 2 + rr] = mbase + mt * 16 + g + 8 * rr;

    const uint32_t sbA = smem_u32(sm) + OF_A * 4;
    uint32_t lmaddr[2];   // ldmatrix byte address per mt (ktp col added in loop)
#pragma unroll
    for (int mt = 0; mt < 2; mt++) {
        int row_in = mbase + mt * 16 + (lane & 7) + ((lane >> 3) & 1) * 8;
        lmaddr[mt] = sbA + (uint32_t)row_in * 528u + ((lane >> 4) & 1) * 16u;
    }
    const uint4* Bq1 = (const uint4*)(sm + OF_B1);
    const uint4* Bq2 = (const uint4*)(sm + OF_B2);

    float c1[8], c2[8];
#pragma unroll
    for (int i = 0; i < 8; i++) { c1[i] = 0.f; c2[i] = 0.f; }

    for (int n = 0; n <= SEQT; n++) {
        uint32_t* ghw = g_h[n & 1];     // this iteration's exchange buffer

        // prefetch x(n) early (consumed after MMA)
        float xtv[4];
        if (n < SEQT) {
#pragma unroll
            for (int e = 0; e < 4; e++) xtv[e] = __ldcg(&g_xT[n * BATCH + b0 + rows[e]]);
        }

        float acc1[4][2][4], acc2[4][2][4];
#pragma unroll
        for (int a1 = 0; a1 < 4; a1++)
#pragma unroll
            for (int a2 = 0; a2 < 2; a2++)
#pragma unroll
                for (int a3 = 0; a3 < 4; a3++) { acc1[a1][a2][a3] = 0.f; acc2[a1][a2][a3] = 0.f; }

        // ---- k chunks 0..7 : A cols 0:128 = h1(n-1), feeds gates1 AND gates2 ----
#pragma unroll 2
        for (int ktp = 0; ktp < 8; ktp++) {
            uint4 b1a = Bq1[((qh * 8 + ktp) * 2 + 0) * 32 + lane];
            uint4 b1b = Bq1[((qh * 8 + ktp) * 2 + 1) * 32 + lane];
            uint4 b2a = Bq2[((qh * 16 + ktp) * 2 + 0) * 32 + lane];
            uint4 b2b = Bq2[((qh * 16 + ktp) * 2 + 1) * 32 + lane];
#pragma unroll
            for (int mt = 0; mt < 2; mt++) {
                uint32_t af[4];
                ldmA(af, lmaddr[mt] + ktp * 32u);
                mmaf16(acc1[0][mt], af, b1a.x, b1a.y);
                mmaf16(acc1[1][mt], af, b1a.z, b1a.w);
                mmaf16(acc1[2][mt], af, b1b.x, b1b.y);
                mmaf16(acc1[3][mt], af, b1b.z, b1b.w);
                mmaf16(acc2[0][mt], af, b2a.x, b2a.y);
                mmaf16(acc2[1][mt], af, b2a.z, b2a.w);
                mmaf16(acc2[2][mt], af, b2b.x, b2b.y);
                mmaf16(acc2[3][mt], af, b2b.z, b2b.w);
            }
        }
        // ---- k chunks 8..15 : A cols 128:256 = h2(n-2), gates2 only ----
#pragma unroll 2
        for (int ktp = 8; ktp < 16; ktp++) {
            uint4 b2a = Bq2[((qh * 16 + ktp) * 2 + 0) * 32 + lane];
            uint4 b2b = Bq2[((qh * 16 + ktp) * 2 + 1) * 32 + lane];
#pragma unroll
            for (int mt = 0; mt < 2; mt++) {
                uint32_t af[4];
                ldmA(af, lmaddr[mt] + ktp * 32u);
                mmaf16(acc2[0][mt], af, b2a.x, b2a.y);
                mmaf16(acc2[1][mt], af, b2a.z, b2a.w);
                mmaf16(acc2[2][mt], af, b2b.x, b2b.y);
                mmaf16(acc2[3][mt], af, b2b.z, b2b.w);
            }
        }

        // ---- epilogue 1: layer-1 cell for t=n ----
        if (n < SEQT) {
#pragma unroll
            for (int mt = 0; mt < 2; mt++)
#pragma unroll
                for (int rr = 0; rr < 2; rr++) {
                    int e = mt * 2 + rr;
                    float hv[2];
#pragma unroll
                    for (int qq = 0; qq < 2; qq++) {
                        int fr = rr * 2 + qq;
                        int qloc = qh * 8 + tq * 2 + qq;
                        float gi = acc1[0][mt][fr] + xtv[e] * WX[qloc]      + BB1[qloc];
                        float gf = acc1[1][mt][fr] + xtv[e] * WX[16 + qloc] + BB1[16 + qloc];
                        float gg = acc1[2][mt][fr] + xtv[e] * WX[32 + qloc] + BB1[32 + qloc];
                        float go = acc1[3][mt][fr] + xtv[e] * WX[48 + qloc] + BB1[48 + qloc];
                        float iv = sigf(gi), fv = sigf(gf), gv = tanhe(gg), ov = sigf(go);
                        int ci = e * 2 + qq;
                        c1[ci] = fv * c1[ci] + iv * gv;
                        hv[qq] = ov * tanhe(c1[ci]);
                    }
                    __half2 hp = __floats2half2_rn(hv[0], hv[1]);
                    ghw[(size_t)(b0 + rows[e]) * 128 + rank * 8 + qh * 4 + tq] = *(uint32_t*)&hp;
                }
        }
        // ---- epilogue 2: layer-2 cell for t=n-1 ----
        if (n > 0) {
#pragma unroll
            for (int mt = 0; mt < 2; mt++)
#pragma unroll
                for (int rr = 0; rr < 2; rr++) {
                    int e = mt * 2 + rr;
                    float hv[2];
#pragma unroll
                    for (int qq = 0; qq < 2; qq++) {
                        int fr = rr * 2 + qq;
                        int qloc = qh * 8 + tq * 2 + qq;
                        float gi = acc2[0][mt][fr] + BB2[qloc];
                        float gf = acc2[1][mt][fr] + BB2[16 + qloc];
                        float gg = acc2[2][mt][fr] + BB2[32 + qloc];
                        float go = acc2[3][mt][fr] + BB2[48 + qloc];
                        float iv = sigf(gi), fv = sigf(gf), gv = tanhe(gg), ov = sigf(go);
                        int ci = e * 2 + qq;
                        c2[ci] = fv * c2[ci] + iv * gv;
                        hv[qq] = ov * tanhe(c2[ci]);
                    }
                    __half2 hp = __floats2half2_rn(hv[0], hv[1]);
                    ghw[(size_t)(b0 + rows[e]) * 128 + 64 + rank * 8 + qh * 4 + tq] = *(uint32_t*)&hp;
                }
        } else {
            // h2(-1) = 0 (c2 untouched)
#pragma unroll
            for (int e = 0; e < 4; e++)
                ghw[(size_t)(b0 + rows[e]) * 128 + 64 + rank * 8 + qh * 4 + tq] = 0u;
        }

        if (n < SEQT) {
            // exchange: cluster release/acquire orders the STGs vs peers' __ldcg gathers
            CLUSTER_ARRIVE();
            CLUSTER_WAIT();
            // gather full [h1(n) | h2(n-1)] into A tile: each thread copies a 64-word half-row
            {
                int r = tid >> 1, half = tid & 1;
                const uint4* src = (const uint4*)(ghw + (size_t)(b0 + r) * 128 + half * 64);
                uint4* dst = (uint4*)(sm + OF_A + r * SAW + half * 64);
#pragma unroll
                for (int j = 0; j < 16; j++) dst[j] = __ldcg(src + j);
            }
            __syncthreads();
        }
    }

    // ---- final linear: out[b] = h2[b,:] . Wl + bl ----
    CLUSTER_ARRIVE();
    CLUSTER_WAIT();
    if (rank == 0 && tid < MROWS) {
        const uint32_t* hr = g_h[SEQT & 1] + (size_t)(b0 + tid) * 128 + 64;
        float acc = bl[0];
#pragma unroll 16
        for (int w = 0; w < 64; w++) {
            uint32_t u = __ldcg(&hr[w]);
            float2 f = __half22float2(*(__half2*)&u);
            acc += f.x * Wl[2 * w] + f.y * Wl[2 * w + 1];
        }
        out[b0 + tid] = acc;
    }
}

// ======================= launch =======================
extern "C" void kernel_launch(void* const* d_in, const int* in_sizes, int n_in,
                              void* d_out, int out_size) {
    const float* x    = (const float*)d_in[0];
    const float* Wih1 = (const float*)d_in[1];
    const float* Whh1 = (const float*)d_in[2];
    const float* bih1 = (const float*)d_in[3];
    const float* bhh1 = (const float*)d_in[4];
    const float* Wih2 = (const float*)d_in[5];
    const float* Whh2 = (const float*)d_in[6];
    const float* bih2 = (const float*)d_in[7];
    const float* bhh2 = (const float*)d_in[8];
    const float* Wl   = (const float*)d_in[9];
    const float* bl   = (const float*)d_in[10];
    float* out = (float*)d_out;

    cudaFuncSetAttribute(lstm2_kernel, cudaFuncAttributeMaxDynamicSharedMemorySize, SMEM_BYTES);

    xT_kernel<<<(BATCH * SEQT + 255) / 256, 256>>>(x);
    lstm2_kernel<<<(BATCH / MROWS) * CL, NTHREADS, SMEM_BYTES>>>(
        Wih1, Whh1, bih1, bhh1, Wih2, Whh2, bih2, bhh2, Wl, bl, out);
}